// round 1
// baseline (speedup 1.0000x reference)
#include <cuda_runtime.h>

// Projection: per row i of x[N,128]:
//   sq = sum(x_i^2); s = (sq-1)/(sq+1); out_i = [(1-s)*x_i, s]  -> out[N,129]
// Note (1-s) = 2/(1+sq).
//
// One warp per row. Lane t handles elements t, t+32, t+64, t+96 so every
// global load/store is a fully coalesced 128B transaction. Output row stride
// is 129 floats (516B, not 16B aligned) so scalar stores in this pattern are
// the clean way to stay coalesced for all rows.

#ifndef D
#define D 128
#endif

__global__ void __launch_bounds__(256) projection_kernel(
    const float* __restrict__ x, float* __restrict__ out, int n_rows)
{
    const int warp_in_block = threadIdx.x >> 5;
    const int lane = threadIdx.x & 31;
    const int row = blockIdx.x * (blockDim.x >> 5) + warp_in_block;
    if (row >= n_rows) return;

    const float* xr = x + (long long)row * D;

    // Front-batched coalesced loads (MLP=4)
    float v0 = xr[lane];
    float v1 = xr[lane + 32];
    float v2 = xr[lane + 64];
    float v3 = xr[lane + 96];

    float sq = v0 * v0 + v1 * v1 + v2 * v2 + v3 * v3;

    // Warp reduction
    #pragma unroll
    for (int off = 16; off > 0; off >>= 1)
        sq += __shfl_xor_sync(0xFFFFFFFFu, sq, off);

    const float inv   = 1.0f / (1.0f + sq);
    const float scale = 2.0f * inv;          // = 1 - s
    const float s     = (sq - 1.0f) * inv;

    float* orow = out + (long long)row * (D + 1);
    orow[lane]      = scale * v0;
    orow[lane + 32] = scale * v1;
    orow[lane + 64] = scale * v2;
    orow[lane + 96] = scale * v3;
    if (lane == 0) orow[D] = s;
}

extern "C" void kernel_launch(void* const* d_in, const int* in_sizes, int n_in,
                              void* d_out, int out_size)
{
    const float* x = (const float*)d_in[0];
    float* out = (float*)d_out;
    const int n_rows = in_sizes[0] / D;   // 1048576

    const int threads = 256;              // 8 warps = 8 rows per block
    const int rows_per_block = threads / 32;
    const int blocks = (n_rows + rows_per_block - 1) / rows_per_block;
    projection_kernel<<<blocks, threads>>>(x, out, n_rows);
}